// round 4
// baseline (speedup 1.0000x reference)
#include <cuda_runtime.h>

// CRF forward (log-partition) + Viterbi decode, fused.
// B=512 batches, T=1024 steps, K=48 states. One CTA per batch, 64 threads
// (48 active "next-state" threads). Transitions row + exp(transitions) row
// held in registers per thread. Backpointers in shared memory (uint8).
//
// Output layout (float32): [logz(B) | scores(B) | paths(B*T)]

#define Bc 512
#define Tc 1024
#define Kc 48
#define START_T 46
#define END_T 47
#define NEGV (-10000.0f)

#define SMEM_BPTR (Tc * Kc)                 // 49152 bytes
#define SMEM_BYTES (SMEM_BPTR + 48*4 + 48*4 + 16*4)

__device__ __forceinline__ float ninf() { return __int_as_float(0xff800000); }

__global__ void __launch_bounds__(64, 4)
crf_fused_kernel(const float* __restrict__ feats,
                 const float* __restrict__ trans,
                 float* __restrict__ out)
{
    extern __shared__ unsigned char smem[];
    unsigned char* bptr = smem;                                   // [T][48] uint8
    float* w_sh = (float*)(smem + SMEM_BPTR);                     // 48 floats (exp weights / final alpha)
    float* v_sh = (float*)(smem + SMEM_BPTR + 48 * 4);            // 48 floats (viterbi values)
    float* red  = (float*)(smem + SMEM_BPTR + 96 * 4);            // 4 floats (double-buffered warp maxes)

    const int b    = blockIdx.x;
    const int tid  = threadIdx.x;
    const int lane = tid & 31;
    const int wid  = tid >> 5;
    const bool act = (tid < Kc);

    // Per-thread transition row (masked) and its exp, in registers.
    float TR[Kc];
    float E[Kc];
    if (act) {
#pragma unroll
        for (int p = 0; p < Kc; p++) {
            float tv = trans[tid * Kc + p];
            if (tid == START_T) tv = NEGV;   // no transition out of START row target
            if (p == END_T)     tv = NEGV;   // no transition from END as prev
            TR[p] = tv;
            E[p]  = __expf(tv);              // exp(-10000) == 0.0f exactly
        }
    }

    float alpha = act ? ((tid == START_T) ? 0.0f : NEGV) : ninf();
    float v     = alpha;

    const float* fb = feats + (size_t)b * Tc * Kc;

    for (int t = 0; t < Tc; t++) {
        // Emission for this thread's next-state (issue load early).
        float ft = act ? fb[t * Kc + tid] : 0.0f;

        // --- global max of alpha (for stable factored logsumexp) ---
        float am = alpha;
#pragma unroll
        for (int o = 16; o > 0; o >>= 1)
            am = fmaxf(am, __shfl_xor_sync(0xffffffffu, am, o));
        if (lane == 0) red[(t & 1) * 2 + wid] = am;
        __syncthreads();
        float m = fmaxf(red[(t & 1) * 2], red[(t & 1) * 2 + 1]);

        // publish exp-weights and viterbi values
        if (act) {
            w_sh[tid] = __expf(alpha - m);
            v_sh[tid] = v;
        }
        __syncthreads();

        // --- per next-state: S = sum_p w_p * E[p];  viterbi max/argmax ---
        float S0 = 0.f, S1 = 0.f, S2 = 0.f, S3 = 0.f;
        float bb[4] = { ninf(), ninf(), ninf(), ninf() };
        int   ii[4] = { 0, 0, 0, 0 };
        const float4* w4 = (const float4*)w_sh;
        const float4* v4 = (const float4*)v_sh;

#pragma unroll
        for (int h = 0; h < 4; h++) {
#pragma unroll
            for (int q = 0; q < 3; q++) {
                const int p = h * 12 + q * 4;
                float4 wv = w4[p >> 2];
                float4 vv = v4[p >> 2];
                S0 += wv.x * E[p + 0];
                S1 += wv.y * E[p + 1];
                S2 += wv.z * E[p + 2];
                S3 += wv.w * E[p + 3];
                float s0 = vv.x + TR[p + 0];
                if (s0 > bb[h]) { bb[h] = s0; ii[h] = p + 0; }
                float s1 = vv.y + TR[p + 1];
                if (s1 > bb[h]) { bb[h] = s1; ii[h] = p + 1; }
                float s2 = vv.z + TR[p + 2];
                if (s2 > bb[h]) { bb[h] = s2; ii[h] = p + 2; }
                float s3 = vv.w + TR[p + 3];
                if (s3 > bb[h]) { bb[h] = s3; ii[h] = p + 3; }
            }
        }
        // merge chunk trackers; strict '>' keeps first occurrence (ascending p)
        float best = bb[0]; int bi = ii[0];
        if (bb[1] > best) { best = bb[1]; bi = ii[1]; }
        if (bb[2] > best) { best = bb[2]; bi = ii[2]; }
        if (bb[3] > best) { best = bb[3]; bi = ii[3]; }

        if (act) {
            float S = (S0 + S1) + (S2 + S3);
            alpha = m + __logf(S) + ft;      // log(0) -> -inf only for START row; safe
            v     = best + ft;
            bptr[t * Kc + tid] = (unsigned char)bi;
        }
    }

    // publish final alpha / v
    __syncthreads();
    if (act) { w_sh[tid] = alpha; v_sh[tid] = v; }
    __syncthreads();

    if (tid == 0) {
        // logz = logsumexp(alpha + trans[END])
        float mx = ninf();
#pragma unroll
        for (int p = 0; p < Kc; p++) {
            float te = (p == END_T) ? NEGV : trans[END_T * Kc + p];
            float x = w_sh[p] + te;
            mx = fmaxf(mx, x);
        }
        float s = 0.f;
#pragma unroll
        for (int p = 0; p < Kc; p++) {
            float te = (p == END_T) ? NEGV : trans[END_T * Kc + p];
            s += __expf((w_sh[p] + te) - mx);
        }
        float logz = mx + __logf(s);

        // termination: term = v + trans[END]; first-occurrence argmax
        float bestT = ninf(); int last = 0;
#pragma unroll
        for (int p = 0; p < Kc; p++) {
            float te = (p == END_T) ? NEGV : trans[END_T * Kc + p];
            float tm = v_sh[p] + te;
            if (tm > bestT) { bestT = tm; last = p; }
        }

        out[b]      = logz;
        out[Bc + b] = bestT;

        // backtrace
        float* pout = out + 2 * Bc + (size_t)b * Tc;
        int tag = last;
        for (int t = Tc - 1; t >= 0; t--) {
            pout[t] = (float)tag;
            tag = bptr[t * Kc + tag];
        }
    }
}

extern "C" void kernel_launch(void* const* d_in, const int* in_sizes, int n_in,
                              void* d_out, int out_size)
{
    (void)in_sizes; (void)n_in; (void)out_size;
    const float* feats = (const float*)d_in[0];
    const float* trans = (const float*)d_in[1];
    float* out = (float*)d_out;

    cudaFuncSetAttribute(crf_fused_kernel,
                         cudaFuncAttributeMaxDynamicSharedMemorySize, SMEM_BYTES);
    crf_fused_kernel<<<Bc, 64, SMEM_BYTES>>>(feats, trans, out);
}

// round 5
// speedup vs baseline: 1.2237x; 1.2237x over previous
#include <cuda_runtime.h>

// CRF forward (log-partition) + Viterbi decode, fused. Split-K=2 version.
// B=512, T=1024, K=48. One CTA per batch, 96 threads: (state s, half h),
// lane = 2*(s%16)+h so halves pair via shfl_xor(1). Each half handles 24
// prev-states. Lagged scalar normalizer (alpha of state 0) + double-buffered
// publish => ONE __syncthreads per step. Parallel chunked backtrace.
//
// Output layout (float32): [logz(B) | scores(B) | paths(B*T)]

#define Bc 512
#define Tc 1024
#define Kc 48
#define START_T 46
#define END_T 47
#define NEGV (-10000.0f)

#define OFF_BPTR   0
#define SZ_BPTR    (Tc * Kc)                    // 49152
#define OFF_WV     (SZ_BPTR)                    // 2 bufs * 48 * float2 = 768
#define OFF_AFIN   (OFF_WV + 2 * Kc * 8)        // 192
#define OFF_VFIN   (OFF_AFIN + Kc * 4)          // 192
#define OFF_RED    (OFF_VFIN + Kc * 4)          // 16 (2 floats, padded)
#define OFF_MC     (OFF_RED + 16)               // 64*48 = 3072
#define OFF_EC     (OFF_MC + 64 * Kc)           // 64
#define OFF_LAST   (OFF_EC + 64)                // 4
#define SMEM_TOTAL (OFF_LAST + 16)

__device__ __forceinline__ float ninf() { return __int_as_float(0xff800000); }

__global__ void __launch_bounds__(96, 4)
crf_fused_kernel(const float* __restrict__ feats,
                 const float* __restrict__ trans,
                 float* __restrict__ out)
{
    extern __shared__ unsigned char smem[];
    unsigned char* bptr = smem + OFF_BPTR;                 // [T][48] uint8
    float2* wv   = (float2*)(smem + OFF_WV);               // [2][48] (w=exp, v)
    float* a_fin = (float*)(smem + OFF_AFIN);
    float* v_fin = (float*)(smem + OFF_VFIN);
    float* red   = (float*)(smem + OFF_RED);               // [2] alpha of state 0
    unsigned char* Mc = smem + OFF_MC;                     // [64][48] chunk maps
    unsigned char* Ec = smem + OFF_EC;                     // [64] chunk entry tags
    int* lastp = (int*)(smem + OFF_LAST);

    const int b    = blockIdx.x;
    const int tid  = threadIdx.x;
    const int lane = tid & 31;
    const int w    = tid >> 5;
    const int s    = w * 16 + (lane >> 1);   // state 0..47
    const int h    = lane & 1;               // half 0/1
    const int pbase = h * 24;

    // Transition slice (masked) + exp, in registers: p in [pbase, pbase+24)
    float TR[24], E[24];
#pragma unroll
    for (int j = 0; j < 24; j++) {
        int p = pbase + j;
        float tv = trans[s * Kc + p];
        if (s == START_T) tv = NEGV;
        if (p == END_T)   tv = NEGV;
        TR[j] = tv;
        E[j]  = __expf(tv);                  // exp(-10000) == 0.0f exactly
    }

    if (tid == 0) { red[0] = 0.f; red[1] = 0.f; }

    float alpha = (s == START_T) ? 0.0f : NEGV;
    float v     = alpha;
    float m_cur = 0.0f;

    const float* fb = feats + (size_t)b * Tc * Kc + s;
    float ftA = (h == 0) ? fb[0]  : 0.f;
    float ftB = (h == 0) ? fb[Kc] : 0.f;

    for (int t = 0; t < Tc; t++) {
        const int buf = t & 1;
        if (h == 0) {
            float wexp = __expf(alpha - m_cur);    // alpha=-inf -> 0 (safe)
            wv[buf * Kc + s] = make_float2(wexp, v);
        }
        // prefetch feats 2 steps ahead (in-bounds dummy reload at the tail)
        float ftC = (h == 0) ? fb[((t + 2 < Tc) ? (t + 2) : t) * Kc] : 0.f;

        __syncthreads();
        float m_next = red[1 - buf];               // alpha_{t-1}[state 0] (0 early)

        // inner: S = sum_p w_p*E_p ; viterbi max/argmax over 24 candidates
        const float4* wv4 = (const float4*)(wv + buf * Kc) + h * 12;
        float acc0 = 0.f, acc1 = 0.f;
        float b0 = ninf(), b1 = ninf(), b2 = ninf();
        int   i0 = 0, i1 = 0, i2 = 0;
#pragma unroll
        for (int jj = 0; jj < 12; jj++) {
            float4 q = wv4[jj];                    // {w_p, v_p, w_{p+1}, v_{p+1}}
            acc0 = fmaf(q.x, E[2*jj],     acc0);
            acc1 = fmaf(q.z, E[2*jj + 1], acc1);
            float s0 = q.y + TR[2*jj];
            float s1 = q.w + TR[2*jj + 1];
            if (jj < 4) {                          // contiguous chunks => strict '>'
                if (s0 > b0) { b0 = s0; i0 = pbase + 2*jj; }
                if (s1 > b0) { b0 = s1; i0 = pbase + 2*jj + 1; }
            } else if (jj < 8) {
                if (s0 > b1) { b1 = s0; i1 = pbase + 2*jj; }
                if (s1 > b1) { b1 = s1; i1 = pbase + 2*jj + 1; }
            } else {
                if (s0 > b2) { b2 = s0; i2 = pbase + 2*jj; }
                if (s1 > b2) { b2 = s1; i2 = pbase + 2*jj + 1; }
            }
        }
        float best = b0; int bi = i0;
        if (b1 > best) { best = b1; bi = i1; }
        if (b2 > best) { best = b2; bi = i2; }

        float S = acc0 + acc1;
        S += __shfl_xor_sync(0xffffffffu, S, 1);
        float ob = __shfl_xor_sync(0xffffffffu, best, 1);
        int   oi = __shfl_xor_sync(0xffffffffu, bi, 1);
        if (ob > best || (ob == best && oi < bi)) { best = ob; bi = oi; }

        if (h == 0) {
            alpha = m_cur + __logf(S) + ftA;       // log(0) -> -inf only START row
            v     = best + ftA;
            bptr[t * Kc + s] = (unsigned char)bi;
            if (s == 0) red[buf] = alpha;          // normalizer for step t+1
        }
        m_cur = m_next;
        ftA = ftB; ftB = ftC;
    }

    __syncthreads();
    if (h == 0) { a_fin[s] = alpha; v_fin[s] = v; }
    __syncthreads();

    if (tid == 0) {
        // logz = logsumexp(alpha + trans[END])
        float mx = ninf();
#pragma unroll
        for (int p = 0; p < Kc; p++) {
            float te = (p == END_T) ? NEGV : trans[END_T * Kc + p];
            mx = fmaxf(mx, a_fin[p] + te);
        }
        float sum = 0.f;
#pragma unroll
        for (int p = 0; p < Kc; p++) {
            float te = (p == END_T) ? NEGV : trans[END_T * Kc + p];
            sum += __expf((a_fin[p] + te) - mx);
        }
        float logz = mx + __logf(sum);

        // termination: first-occurrence argmax of v + trans[END]
        float bestT = ninf(); int last = 0;
#pragma unroll
        for (int p = 0; p < Kc; p++) {
            float te = (p == END_T) ? NEGV : trans[END_T * Kc + p];
            float tm = v_fin[p] + te;
            if (tm > bestT) { bestT = tm; last = p; }
        }
        out[b]      = logz;
        out[Bc + b] = bestT;
        *lastp = last;
    }
    __syncthreads();

    // ---- Parallel backtrace: 64 chunks of 16 steps ----
    // Phase A: chunk maps Mc[c][e] = tag after walking chunk c from entry e.
    if (tid < 64) {
        const int c = tid;
        for (int half = 0; half < 2; half++) {
            unsigned char tg[24];
#pragma unroll
            for (int e = 0; e < 24; e++) tg[e] = (unsigned char)(half * 24 + e);
            for (int i = 15; i >= 0; i--) {
                const unsigned char* row = bptr + (c * 16 + i) * Kc;
#pragma unroll
                for (int e = 0; e < 24; e++) tg[e] = row[tg[e]];
            }
#pragma unroll
            for (int e = 0; e < 24; e++) Mc[c * Kc + half * 24 + e] = tg[e];
        }
    }
    __syncthreads();
    // Phase B: serial chain over 64 chunks (tid 0)
    if (tid == 0) {
        int tag = *lastp;
        for (int c = 63; c >= 0; c--) {
            Ec[c] = (unsigned char)tag;
            tag = Mc[c * Kc + tag];
        }
    }
    __syncthreads();
    // Phase C: each thread emits its chunk's 16 path entries
    if (tid < 64) {
        const int c = tid;
        float* pout = out + 2 * Bc + (size_t)b * Tc + c * 16;
        int tg = Ec[c];
        for (int i = 15; i >= 0; i--) {
            pout[i] = (float)tg;
            tg = bptr[(c * 16 + i) * Kc + tg];
        }
    }
}

extern "C" void kernel_launch(void* const* d_in, const int* in_sizes, int n_in,
                              void* d_out, int out_size)
{
    (void)in_sizes; (void)n_in; (void)out_size;
    const float* feats = (const float*)d_in[0];
    const float* trans = (const float*)d_in[1];
    float* out = (float*)d_out;

    cudaFuncSetAttribute(crf_fused_kernel,
                         cudaFuncAttributeMaxDynamicSharedMemorySize, SMEM_TOTAL);
    crf_fused_kernel<<<Bc, 96, SMEM_TOTAL>>>(feats, trans, out);
}